// round 8
// baseline (speedup 1.0000x reference)
#include <cuda_runtime.h>
#include <cuda_bf16.h>
#include <math.h>

#define NT   1000
#define NTP  1024
#define H    128
#define B    1024
#define L    256
#define NTILE 16
#define NPAIR (NTILE*(NTILE+1)/2)   // 136 lower-triangle 64x64 tiles
#define ST   136                    // bf16 smem row stride (elements)
// W_out (517,3) row-major: rows 0:128 venue, 128:256 team, 256:384 opp,
// 384:512 result, 512 gf, 513 ga, 514:517 stats.

// ---- device scratch ----
__device__ float  g_G[NTP * NTP];
__device__ float4 g_PT1[NTP];
__device__ float4 g_PT2[NTP];
__device__ float4 g_PVR[9];
__device__ float  g_Gven[9];

// pack two fp32 -> bf16x2 (lo = a, hi = b)
__device__ __forceinline__ unsigned int bf16x2(float a, float b) {
    unsigned int r;
    asm("cvt.rn.bf16x2.f32 %0, %1, %2;" : "=r"(r) : "f"(b), "f"(a));
    return r;
}

// ---------------------------------------------------------------------------
// Kernel 1 (fused, grid = 141):
//   blocks 0..135   : symmetric gram tiles via bf16 mma.sync (fp32 accum)
//   blocks 136..139 : team projections
//   block  140      : 3x3 tables
// ---------------------------------------------------------------------------
__global__ void __launch_bounds__(256) prep_gram_kernel(
    const float* __restrict__ E,
    const float* __restrict__ venue_embed,
    const float* __restrict__ result_embed,
    const float* __restrict__ W) {
    const int bx  = blockIdx.x;
    const int tid = threadIdx.x;

    if (bx < NPAIR) {
        __shared__ __align__(16) char buf[2 * 64 * ST * 2];   // 34816 B
        __nv_bfloat16* Abf = (__nv_bfloat16*)buf;             // 64 x ST
        __nv_bfloat16* Bbf = (__nv_bfloat16*)(buf + 64 * ST * 2);
        float* Csm = (float*)buf;                             // 64 x 68 overlay

        const int ti = (int)floorf((sqrtf(8.0f * bx + 1.0f) - 1.0f) * 0.5f + 1e-4f);
        const int tj = bx - ti * (ti + 1) / 2;
        const int i0 = ti * 64;
        const int j0 = tj * 64;

        // ---- load + convert fp32 -> bf16 (coalesced LDG.128) ----
        const float4 z4 = make_float4(0.f, 0.f, 0.f, 0.f);
        #pragma unroll
        for (int it = 0; it < 8; it++) {
            const int idx = tid + 256 * it;
            const int row = idx >> 5;        // 0..63
            const int q4  = idx & 31;        // float4 col
            const int ri = i0 + row;
            const int rj = j0 + row;
            const float4 a = (ri < NT) ? *(const float4*)(E + ri * H + 4 * q4) : z4;
            const float4 b = (rj < NT) ? *(const float4*)(E + rj * H + 4 * q4) : z4;
            *(unsigned int*)&Abf[row * ST + 4 * q4]     = bf16x2(a.x, a.y);
            *(unsigned int*)&Abf[row * ST + 4 * q4 + 2] = bf16x2(a.z, a.w);
            *(unsigned int*)&Bbf[row * ST + 4 * q4]     = bf16x2(b.x, b.y);
            *(unsigned int*)&Bbf[row * ST + 4 * q4 + 2] = bf16x2(b.z, b.w);
        }
        __syncthreads();

        // ---- mma phase: warp w -> rows m0..m0+15, cols n0..n0+31 ----
        const int l   = tid & 31;
        const int wid = tid >> 5;
        const int m0  = (wid & 3) * 16;
        const int n0  = (wid >> 2) * 32;
        const int lr  = l >> 2;          // 0..7
        const int lc  = (l & 3) * 2;     // 0,2,4,6

        float c[4][4];
        #pragma unroll
        for (int g = 0; g < 4; g++)
            #pragma unroll
            for (int r = 0; r < 4; r++) c[g][r] = 0.0f;

        #pragma unroll
        for (int kk = 0; kk < 8; kk++) {
            const int kb = kk * 16 + lc;
            const unsigned int a0 = *(const unsigned int*)&Abf[(m0 + lr)     * ST + kb];
            const unsigned int a1 = *(const unsigned int*)&Abf[(m0 + lr + 8) * ST + kb];
            const unsigned int a2 = *(const unsigned int*)&Abf[(m0 + lr)     * ST + kb + 8];
            const unsigned int a3 = *(const unsigned int*)&Abf[(m0 + lr + 8) * ST + kb + 8];
            #pragma unroll
            for (int g = 0; g < 4; g++) {
                const unsigned int b0 = *(const unsigned int*)&Bbf[(n0 + 8 * g + lr) * ST + kb];
                const unsigned int b1 = *(const unsigned int*)&Bbf[(n0 + 8 * g + lr) * ST + kb + 8];
                asm("mma.sync.aligned.m16n8k16.row.col.f32.bf16.bf16.f32 "
                    "{%0,%1,%2,%3}, {%4,%5,%6,%7}, {%8,%9}, {%0,%1,%2,%3};"
                    : "+f"(c[g][0]), "+f"(c[g][1]), "+f"(c[g][2]), "+f"(c[g][3])
                    : "r"(a0), "r"(a1), "r"(a2), "r"(a3), "r"(b0), "r"(b1));
            }
        }
        __syncthreads();   // all reads of Abf/Bbf done before Csm overlay

        // C frag layout: c0,c1 -> (m=lr, n=lc+0/1); c2,c3 -> (m=lr+8, n=lc+0/1)
        #pragma unroll
        for (int g = 0; g < 4; g++) {
            const int cn = n0 + 8 * g + lc;
            Csm[(m0 + lr)     * 68 + cn]     = c[g][0];
            Csm[(m0 + lr)     * 68 + cn + 1] = c[g][1];
            Csm[(m0 + lr + 8) * 68 + cn]     = c[g][2];
            Csm[(m0 + lr + 8) * 68 + cn + 1] = c[g][3];
        }
        __syncthreads();

        // ---- coalesced global writes: direct tile ----
        #pragma unroll
        for (int it = 0; it < 4; it++) {
            const int idx = tid + 256 * it;
            const int i  = idx >> 4;        // 0..63
            const int jc = idx & 15;        // float4 col
            const float4 vv = make_float4(Csm[i * 68 + 4 * jc],
                                          Csm[i * 68 + 4 * jc + 1],
                                          Csm[i * 68 + 4 * jc + 2],
                                          Csm[i * 68 + 4 * jc + 3]);
            *(float4*)(g_G + (i0 + i) * NTP + j0 + 4 * jc) = vv;
        }
        // ---- mirror tile (transposed) ----
        if (ti != tj) {
            #pragma unroll
            for (int it = 0; it < 4; it++) {
                const int idx = tid + 256 * it;
                const int j  = idx >> 4;    // 0..63 (mirror row)
                const int ic = idx & 15;    // float4 col along i
                const float4 vv = make_float4(Csm[(4 * ic)     * 68 + j],
                                              Csm[(4 * ic + 1) * 68 + j],
                                              Csm[(4 * ic + 2) * 68 + j],
                                              Csm[(4 * ic + 3) * 68 + j]);
                *(float4*)(g_G + (j0 + j) * NTP + i0 + 4 * ic) = vv;
            }
        }
        return;
    }

    if (bx < NPAIR + 4) {
        const int t = (bx - NPAIR) * 256 + tid;
        if (t < NT) {
            const float4* row = (const float4*)(E + t * H);
            float a0 = 0, a1 = 0, a2 = 0, b0 = 0, b1 = 0, b2 = 0;
            #pragma unroll 8
            for (int k4 = 0; k4 < 32; k4++) {
                const float4 e = row[k4];
                const float ev[4] = {e.x, e.y, e.z, e.w};
                #pragma unroll
                for (int d = 0; d < 4; d++) {
                    const int k = 4 * k4 + d;
                    a0 += ev[d] * W[(128 + k) * 3 + 0];
                    a1 += ev[d] * W[(128 + k) * 3 + 1];
                    a2 += ev[d] * W[(128 + k) * 3 + 2];
                    b0 += ev[d] * W[(256 + k) * 3 + 0];
                    b1 += ev[d] * W[(256 + k) * 3 + 1];
                    b2 += ev[d] * W[(256 + k) * 3 + 2];
                }
            }
            g_PT1[t] = make_float4(a0, a1, a2, 0.0f);
            g_PT2[t] = make_float4(b0, b1, b2, 0.0f);
        }
        return;
    }

    // 3x3 tables: warp per (i,j)
    {
        const int w    = tid >> 5;
        const int lane = tid & 31;
        for (int p = w; p < 9; p += 8) {
            const int i = p / 3, j = p % 3;
            const float4 vi = *(const float4*)(venue_embed  + i * H + 4 * lane);
            const float4 vj = *(const float4*)(venue_embed  + j * H + 4 * lane);
            const float4 re = *(const float4*)(result_embed + j * H + 4 * lane);
            const float4 w0 = *(const float4*)(W + 12 * lane + 0);
            const float4 w1 = *(const float4*)(W + 12 * lane + 4);
            const float4 w2 = *(const float4*)(W + 12 * lane + 8);
            const float4 q0 = *(const float4*)(W + 384 * 3 + 12 * lane + 0);
            const float4 q1 = *(const float4*)(W + 384 * 3 + 12 * lane + 4);
            const float4 q2 = *(const float4*)(W + 384 * 3 + 12 * lane + 8);
            const float viv[4] = {vi.x, vi.y, vi.z, vi.w};
            const float vjv[4] = {vj.x, vj.y, vj.z, vj.w};
            const float rev[4] = {re.x, re.y, re.z, re.w};
            const float wv[12] = {w0.x, w0.y, w0.z, w0.w, w1.x, w1.y, w1.z, w1.w,
                                  w2.x, w2.y, w2.z, w2.w};
            const float qv[12] = {q0.x, q0.y, q0.z, q0.w, q1.x, q1.y, q1.z, q1.w,
                                  q2.x, q2.y, q2.z, q2.w};
            float gv = 0, p0 = 0, p1 = 0, p2 = 0;
            #pragma unroll
            for (int d = 0; d < 4; d++) {
                gv += viv[d] * vjv[d];
                p0 += viv[d] * wv[3 * d + 0] + rev[d] * qv[3 * d + 0];
                p1 += viv[d] * wv[3 * d + 1] + rev[d] * qv[3 * d + 1];
                p2 += viv[d] * wv[3 * d + 2] + rev[d] * qv[3 * d + 2];
            }
            #pragma unroll
            for (int off = 16; off; off >>= 1) {
                gv += __shfl_xor_sync(0xffffffffu, gv, off);
                p0 += __shfl_xor_sync(0xffffffffu, p0, off);
                p1 += __shfl_xor_sync(0xffffffffu, p1, off);
                p2 += __shfl_xor_sync(0xffffffffu, p2, off);
            }
            if (lane == 0) {
                g_Gven[p] = gv;
                g_PVR[p]  = make_float4(p0, p1, p2, 0.0f);
            }
        }
    }
}

// ---------------------------------------------------------------------------
// Kernel 2: main — warp per batch (R6 variant, best measured).
// Dynamic smem (floats):
//   [0, 16384)       rows[8][2][1024]
//   [16384, 20480)   PT1s (1024 float4)
//   [20480, 24576)   PT2s (1024 float4)
//   [24576, 24612)   PVRs (9 float4)
//   [24612, 24621)   Gvens (9 float)
// ---------------------------------------------------------------------------
#define MAIN_SMEM_BYTES (24624 * 4)

__global__ void __launch_bounds__(256, 1) main_kernel(
    const int* __restrict__ venue, const int* __restrict__ team,
    const int* __restrict__ opp,   const int* __restrict__ result,
    const float* __restrict__ gf,  const float* __restrict__ ga,
    const float* __restrict__ stats,
    const int* __restrict__ next_venue, const int* __restrict__ next_team,
    const int* __restrict__ next_opp,
    const float* __restrict__ W, const float* __restrict__ b_out,
    float* __restrict__ out) {

    extern __shared__ float sm[];
    float*  rows  = sm;
    float4* PT1s  = (float4*)(sm + 16384);
    float4* PT2s  = (float4*)(sm + 20480);
    float4* PVRs  = (float4*)(sm + 24576);
    float*  Gvens = sm + 24612;

    const int tid  = threadIdx.x;
    const int lane = tid & 31;
    const int w    = tid >> 5;
    const int b    = blockIdx.x * 8 + w;

    const int nv = next_venue[b];
    const int nt = next_team[b];
    const int no = next_opp[b];

    // ---- stage this warp's two Gram rows (coalesced) ----
    const float4* src1 = (const float4*)(g_G + nt * NTP);
    const float4* src2 = (const float4*)(g_G + no * NTP);
    float4* dst1 = (float4*)(rows + w * 2048);
    float4* dst2 = (float4*)(rows + w * 2048 + 1024);
    #pragma unroll
    for (int i = 0; i < 8; i++) {
        dst1[lane + 32 * i] = src1[lane + 32 * i];
        dst2[lane + 32 * i] = src2[lane + 32 * i];
    }
    // ---- stage tables (block-cooperative, coalesced) ----
    #pragma unroll
    for (int i = 0; i < 4; i++) {
        PT1s[tid + 256 * i] = g_PT1[tid + 256 * i];
        PT2s[tid + 256 * i] = g_PT2[tid + 256 * i];
    }
    if (tid < 9) { PVRs[tid] = g_PVR[tid]; Gvens[tid] = g_Gven[tid]; }

    // ---- stream loads: two contiguous 4-groups per thread ----
    const int idx0 = b * L + lane * 4;
    const int idx1 = idx0 + 128;
    const int4   v4a  = *(const int4*)(venue  + idx0);
    const int4   t4a  = *(const int4*)(team   + idx0);
    const int4   o4a  = *(const int4*)(opp    + idx0);
    const int4   r4a  = *(const int4*)(result + idx0);
    const float4 gf4a = *(const float4*)(gf + idx0);
    const float4 ga4a = *(const float4*)(ga + idx0);
    const int4   v4b  = *(const int4*)(venue  + idx1);
    const int4   t4b  = *(const int4*)(team   + idx1);
    const int4   o4b  = *(const int4*)(opp    + idx1);
    const int4   r4b  = *(const int4*)(result + idx1);
    const float4 gf4b = *(const float4*)(gf + idx1);
    const float4 ga4b = *(const float4*)(ga + idx1);

    const int   vv[8]  = {v4a.x, v4a.y, v4a.z, v4a.w, v4b.x, v4b.y, v4b.z, v4b.w};
    const int   tt[8]  = {t4a.x, t4a.y, t4a.z, t4a.w, t4b.x, t4b.y, t4b.z, t4b.w};
    const int   oo[8]  = {o4a.x, o4a.y, o4a.z, o4a.w, o4b.x, o4b.y, o4b.z, o4b.w};
    const int   rr[8]  = {r4a.x, r4a.y, r4a.z, r4a.w, r4b.x, r4b.y, r4b.z, r4b.w};
    const float gfv[8] = {gf4a.x, gf4a.y, gf4a.z, gf4a.w, gf4b.x, gf4b.y, gf4b.z, gf4b.w};
    const float gav[8] = {ga4a.x, ga4a.y, ga4a.z, ga4a.w, ga4b.x, ga4b.y, ga4b.z, ga4b.w};

    __syncthreads();

    const float* rw0 = rows + w * 2048;
    const float* rw1 = rows + w * 2048 + 1024;

    const float inv_scale = 0.051031036307982884f;  // 1/sqrt(384)
    float s[8];
    #pragma unroll
    for (int j = 0; j < 8; j++)
        s[j] = (Gvens[vv[j] * 3 + nv] + rw0[tt[j]] + rw1[oo[j]]) * inv_scale;

    float m = s[0];
    #pragma unroll
    for (int j = 1; j < 8; j++) m = fmaxf(m, s[j]);
    #pragma unroll
    for (int off = 16; off; off >>= 1)
        m = fmaxf(m, __shfl_xor_sync(0xffffffffu, m, off));

    float e[8], su = 0.0f;
    #pragma unroll
    for (int j = 0; j < 8; j++) { e[j] = __expf(s[j] - m); su += e[j]; }
    #pragma unroll
    for (int off = 16; off; off >>= 1)
        su += __shfl_xor_sync(0xffffffffu, su, off);
    const float inv = __frcp_rn(su);

    const float wgf0 = W[512 * 3 + 0], wgf1 = W[512 * 3 + 1], wgf2 = W[512 * 3 + 2];
    const float wga0 = W[513 * 3 + 0], wga1 = W[513 * 3 + 1], wga2 = W[513 * 3 + 2];

    float c0 = 0, c1 = 0, c2 = 0;
    #pragma unroll
    for (int j = 0; j < 8; j++) {
        const float a = e[j] * inv;
        const float4 p1  = PT1s[tt[j]];
        const float4 p2  = PT2s[oo[j]];
        const float4 pvr = PVRs[vv[j] * 3 + rr[j]];
        c0 += a * (p1.x + p2.x + pvr.x + gfv[j] * wgf0 + gav[j] * wga0);
        c1 += a * (p1.y + p2.y + pvr.y + gfv[j] * wgf1 + gav[j] * wga1);
        c2 += a * (p1.z + p2.z + pvr.z + gfv[j] * wgf2 + gav[j] * wga2);
    }
    #pragma unroll
    for (int off = 16; off; off >>= 1) {
        c0 += __shfl_xor_sync(0xffffffffu, c0, off);
        c1 += __shfl_xor_sync(0xffffffffu, c1, off);
        c2 += __shfl_xor_sync(0xffffffffu, c2, off);
    }

    if (lane == 0) {
        const float s0 = stats[b * 3 + 0], s1 = stats[b * 3 + 1], s2 = stats[b * 3 + 2];
        c0 += s0 * W[514 * 3 + 0] + s1 * W[515 * 3 + 0] + s2 * W[516 * 3 + 0] + b_out[0];
        c1 += s0 * W[514 * 3 + 1] + s1 * W[515 * 3 + 1] + s2 * W[516 * 3 + 1] + b_out[1];
        c2 += s0 * W[514 * 3 + 2] + s1 * W[515 * 3 + 2] + s2 * W[516 * 3 + 2] + b_out[2];
        out[b * 3 + 0] = c0;
        out[b * 3 + 1] = c1;
        out[b * 3 + 2] = c2;
    }
}

// ---------------------------------------------------------------------------
extern "C" void kernel_launch(void* const* d_in, const int* in_sizes, int n_in,
                              void* d_out, int out_size) {
    const float* team_embed    = (const float*)d_in[0];
    const float* venue_embed   = (const float*)d_in[1];
    const float* result_embed  = (const float*)d_in[2];
    const float* W_out         = (const float*)d_in[3];
    const float* b_out         = (const float*)d_in[4];
    const float* goals_for     = (const float*)d_in[5];
    const float* goals_against = (const float*)d_in[6];
    const float* stats         = (const float*)d_in[7];
    const int*   venue         = (const int*)d_in[8];
    const int*   team          = (const int*)d_in[9];
    const int*   opponent      = (const int*)d_in[10];
    const int*   result        = (const int*)d_in[11];
    const int*   next_venue    = (const int*)d_in[12];
    const int*   next_team     = (const int*)d_in[13];
    const int*   next_opponent = (const int*)d_in[14];
    float* out = (float*)d_out;

    cudaFuncSetAttribute(main_kernel,
                         cudaFuncAttributeMaxDynamicSharedMemorySize,
                         MAIN_SMEM_BYTES);

    prep_gram_kernel<<<NPAIR + 5, 256>>>(team_embed, venue_embed,
                                         result_embed, W_out);

    main_kernel<<<128, 256, MAIN_SMEM_BYTES>>>(
        venue, team, opponent, result,
        goals_for, goals_against, stats,
        next_venue, next_team, next_opponent,
        W_out, b_out, out);
}

// round 9
// speedup vs baseline: 1.1201x; 1.1201x over previous
#include <cuda_runtime.h>
#include <math.h>

#define NT   1000
#define NTP  1024
#define H    128
#define B    1024
#define L    256
#define NTILE 16
#define NPAIR (NTILE*(NTILE+1)/2)   // 136 lower-triangle 64x64 tiles
#define NBLK (NPAIR + 5)            // 141 prep blocks
#define NQ   ((B * L) / 4)          // 65536 quads
#define QCHUNK ((NQ + NBLK - 1) / NBLK)   // 465
// W_out (517,3) row-major: rows 0:128 venue, 128:256 team, 256:384 opp,
// 384:512 result, 512 gf, 513 ga, 514:517 stats.

// ---- device scratch ----
__device__ float        g_G[NTP * NTP];
__device__ float4       g_PT1[NTP];
__device__ float4       g_PT2[NTP];
__device__ float4       g_PVR[9];
__device__ float        g_Gven[9];
__device__ unsigned int g_pidx[B * L];     // v | t<<2 | o<<12 | r<<22
__device__ float2       g_pgoals[B * L];   // (gf, ga)

// ---------------------------------------------------------------------------
// Kernel 1 (fused, grid = 141):
//   blocks 0..135   : symmetric gram tiles (f32x2 FMA, both k-halves preloaded)
//   blocks 136..139 : team projections
//   block  140      : 3x3 tables
//   ALL blocks      : tail = pack 1/141 of the main-kernel stream data
// ---------------------------------------------------------------------------
__global__ void __launch_bounds__(256) prep_gram_kernel(
    const float* __restrict__ E,
    const float* __restrict__ venue_embed,
    const float* __restrict__ result_embed,
    const float* __restrict__ W,
    const int* __restrict__ venue, const int* __restrict__ team,
    const int* __restrict__ opp,   const int* __restrict__ result,
    const float* __restrict__ gf,  const float* __restrict__ ga) {
    const int bx  = blockIdx.x;
    const int tid = threadIdx.x;

    if (bx < NPAIR) {
        __shared__ float As[64 * 68];
        __shared__ float Bs[64 * 68];
        const int ti = (int)floorf((sqrtf(8.0f * bx + 1.0f) - 1.0f) * 0.5f + 1e-4f);
        const int tj = bx - ti * (ti + 1) / 2;
        const int i0 = ti * 64;
        const int j0 = tj * 64;
        const int tx = tid & 15;
        const int ty = tid >> 4;

        // preload BOTH k-halves: 16 LDG.128 in flight
        float4 ra[2][4], rb[2][4];
        const float4 z4 = make_float4(0.f, 0.f, 0.f, 0.f);
        #pragma unroll
        for (int h = 0; h < 2; h++) {
            #pragma unroll
            for (int i = 0; i < 4; i++) {
                const int idx = tid + 256 * i;
                const int t  = idx >> 4;
                const int k4 = idx & 15;
                const int ri = i0 + t;
                const int rj = j0 + t;
                ra[h][i] = (ri < NT) ? *(const float4*)(E + ri * H + 64 * h + 4 * k4) : z4;
                rb[h][i] = (rj < NT) ? *(const float4*)(E + rj * H + 64 * h + 4 * k4) : z4;
            }
        }

        unsigned long long accp[4][2];
        #pragma unroll
        for (int u = 0; u < 4; u++) { accp[u][0] = 0ull; accp[u][1] = 0ull; }

        #pragma unroll
        for (int h = 0; h < 2; h++) {
            if (h) __syncthreads();
            #pragma unroll
            for (int i = 0; i < 4; i++) {
                const int idx = tid + 256 * i;
                const int t  = idx >> 4;
                const int k4 = idx & 15;
                const int c  = t ^ (4 * (k4 & 7));
                const int r0 = 4 * k4;
                As[(r0 + 0) * 68 + c] = ra[h][i].x;
                As[(r0 + 1) * 68 + c] = ra[h][i].y;
                As[(r0 + 2) * 68 + c] = ra[h][i].z;
                As[(r0 + 3) * 68 + c] = ra[h][i].w;
                Bs[(r0 + 0) * 68 + c] = rb[h][i].x;
                Bs[(r0 + 1) * 68 + c] = rb[h][i].y;
                Bs[(r0 + 2) * 68 + c] = rb[h][i].z;
                Bs[(r0 + 3) * 68 + c] = rb[h][i].w;
            }
            __syncthreads();

            #pragma unroll 16
            for (int k = 0; k < 64; k++) {
                const int cc = (k >> 2) & 7;
                const float4 a4 = *(const float4*)&As[k * 68 + 4 * (ty ^ cc)];
                const ulonglong2 b2 = *(const ulonglong2*)&Bs[k * 68 + 4 * (tx ^ cc)];
                const unsigned int au[4] = {
                    __float_as_uint(a4.x), __float_as_uint(a4.y),
                    __float_as_uint(a4.z), __float_as_uint(a4.w)};
                #pragma unroll
                for (int u = 0; u < 4; u++) {
                    unsigned long long ap;
                    asm("mov.b64 %0, {%1, %1};" : "=l"(ap) : "r"(au[u]));
                    asm("fma.rn.f32x2 %0, %1, %2, %0;"
                        : "+l"(accp[u][0]) : "l"(ap), "l"(b2.x));
                    asm("fma.rn.f32x2 %0, %1, %2, %0;"
                        : "+l"(accp[u][1]) : "l"(ap), "l"(b2.y));
                }
            }
        }

        float acc[4][4];
        #pragma unroll
        for (int u = 0; u < 4; u++) {
            unsigned int lo, hi;
            asm("mov.b64 {%0, %1}, %2;" : "=r"(lo), "=r"(hi) : "l"(accp[u][0]));
            acc[u][0] = __uint_as_float(lo); acc[u][1] = __uint_as_float(hi);
            asm("mov.b64 {%0, %1}, %2;" : "=r"(lo), "=r"(hi) : "l"(accp[u][1]));
            acc[u][2] = __uint_as_float(lo); acc[u][3] = __uint_as_float(hi);
        }

        float4* G4 = (float4*)g_G;
        #pragma unroll
        for (int u = 0; u < 4; u++) {
            const int i = i0 + 4 * ty + u;
            G4[(i * NTP + j0) / 4 + tx] =
                make_float4(acc[u][0], acc[u][1], acc[u][2], acc[u][3]);
        }
        if (ti != tj) {
            #pragma unroll
            for (int v = 0; v < 4; v++) {
                const int j = j0 + 4 * tx + v;
                G4[(j * NTP + i0) / 4 + ty] =
                    make_float4(acc[0][v], acc[1][v], acc[2][v], acc[3][v]);
            }
        }
    } else if (bx < NPAIR + 4) {
        const int t = (bx - NPAIR) * 256 + tid;
        if (t < NT) {
            const float4* row = (const float4*)(E + t * H);
            float a0 = 0, a1 = 0, a2 = 0, b0 = 0, b1 = 0, b2 = 0;
            #pragma unroll 8
            for (int k4 = 0; k4 < 32; k4++) {
                const float4 e = row[k4];
                const float ev[4] = {e.x, e.y, e.z, e.w};
                #pragma unroll
                for (int d = 0; d < 4; d++) {
                    const int k = 4 * k4 + d;
                    a0 += ev[d] * W[(128 + k) * 3 + 0];
                    a1 += ev[d] * W[(128 + k) * 3 + 1];
                    a2 += ev[d] * W[(128 + k) * 3 + 2];
                    b0 += ev[d] * W[(256 + k) * 3 + 0];
                    b1 += ev[d] * W[(256 + k) * 3 + 1];
                    b2 += ev[d] * W[(256 + k) * 3 + 2];
                }
            }
            g_PT1[t] = make_float4(a0, a1, a2, 0.0f);
            g_PT2[t] = make_float4(b0, b1, b2, 0.0f);
        }
    } else {
        // 3x3 tables: warp per (i,j)
        const int w    = tid >> 5;
        const int lane = tid & 31;
        for (int p = w; p < 9; p += 8) {
            const int i = p / 3, j = p % 3;
            const float4 vi = *(const float4*)(venue_embed  + i * H + 4 * lane);
            const float4 vj = *(const float4*)(venue_embed  + j * H + 4 * lane);
            const float4 re = *(const float4*)(result_embed + j * H + 4 * lane);
            const float4 w0 = *(const float4*)(W + 12 * lane + 0);
            const float4 w1 = *(const float4*)(W + 12 * lane + 4);
            const float4 w2 = *(const float4*)(W + 12 * lane + 8);
            const float4 q0 = *(const float4*)(W + 384 * 3 + 12 * lane + 0);
            const float4 q1 = *(const float4*)(W + 384 * 3 + 12 * lane + 4);
            const float4 q2 = *(const float4*)(W + 384 * 3 + 12 * lane + 8);
            const float viv[4] = {vi.x, vi.y, vi.z, vi.w};
            const float vjv[4] = {vj.x, vj.y, vj.z, vj.w};
            const float rev[4] = {re.x, re.y, re.z, re.w};
            const float wv[12] = {w0.x, w0.y, w0.z, w0.w, w1.x, w1.y, w1.z, w1.w,
                                  w2.x, w2.y, w2.z, w2.w};
            const float qv[12] = {q0.x, q0.y, q0.z, q0.w, q1.x, q1.y, q1.z, q1.w,
                                  q2.x, q2.y, q2.z, q2.w};
            float gv = 0, p0 = 0, p1 = 0, p2 = 0;
            #pragma unroll
            for (int d = 0; d < 4; d++) {
                gv += viv[d] * vjv[d];
                p0 += viv[d] * wv[3 * d + 0] + rev[d] * qv[3 * d + 0];
                p1 += viv[d] * wv[3 * d + 1] + rev[d] * qv[3 * d + 1];
                p2 += viv[d] * wv[3 * d + 2] + rev[d] * qv[3 * d + 2];
            }
            #pragma unroll
            for (int off = 16; off; off >>= 1) {
                gv += __shfl_xor_sync(0xffffffffu, gv, off);
                p0 += __shfl_xor_sync(0xffffffffu, p0, off);
                p1 += __shfl_xor_sync(0xffffffffu, p1, off);
                p2 += __shfl_xor_sync(0xffffffffu, p2, off);
            }
            if (lane == 0) {
                g_Gven[p] = gv;
                g_PVR[p]  = make_float4(p0, p1, p2, 0.0f);
            }
        }
    }

    // ---- tail: pack this block's slice of the stream data ----
    {
        const int qend = min((bx + 1) * QCHUNK, NQ);
        for (int q = bx * QCHUNK + tid; q < qend; q += 256) {
            const int4   v4 = ((const int4*)venue)[q];
            const int4   t4 = ((const int4*)team)[q];
            const int4   o4 = ((const int4*)opp)[q];
            const int4   r4 = ((const int4*)result)[q];
            const float4 g4 = ((const float4*)gf)[q];
            const float4 a4 = ((const float4*)ga)[q];
            uint4 p;
            p.x = (unsigned)v4.x | ((unsigned)t4.x << 2) | ((unsigned)o4.x << 12) | ((unsigned)r4.x << 22);
            p.y = (unsigned)v4.y | ((unsigned)t4.y << 2) | ((unsigned)o4.y << 12) | ((unsigned)r4.y << 22);
            p.z = (unsigned)v4.z | ((unsigned)t4.z << 2) | ((unsigned)o4.z << 12) | ((unsigned)r4.z << 22);
            p.w = (unsigned)v4.w | ((unsigned)t4.w << 2) | ((unsigned)o4.w << 12) | ((unsigned)r4.w << 22);
            ((uint4*)g_pidx)[q] = p;
            ((float4*)g_pgoals)[2 * q]     = make_float4(g4.x, a4.x, g4.y, a4.y);
            ((float4*)g_pgoals)[2 * q + 1] = make_float4(g4.z, a4.z, g4.w, a4.w);
        }
    }
}

// ---------------------------------------------------------------------------
// Kernel 2: main — warp per batch, packed streams.
// Dynamic smem (floats):
//   [0, 16384)       rows[8][2][1024]
//   [16384, 20480)   PT1s (1024 float4)
//   [20480, 24576)   PT2s (1024 float4)
//   [24576, 24612)   PVRs (9 float4)
//   [24612, 24621)   Gvens (9 float)
// ---------------------------------------------------------------------------
#define MAIN_SMEM_BYTES (24624 * 4)

__global__ void __launch_bounds__(256, 1) main_kernel(
    const float* __restrict__ stats,
    const int* __restrict__ next_venue, const int* __restrict__ next_team,
    const int* __restrict__ next_opp,
    const float* __restrict__ W, const float* __restrict__ b_out,
    float* __restrict__ out) {

    extern __shared__ float sm[];
    float*  rows  = sm;
    float4* PT1s  = (float4*)(sm + 16384);
    float4* PT2s  = (float4*)(sm + 20480);
    float4* PVRs  = (float4*)(sm + 24576);
    float*  Gvens = sm + 24612;

    const int tid  = threadIdx.x;
    const int lane = tid & 31;
    const int w    = tid >> 5;
    const int b    = blockIdx.x * 8 + w;

    const int nv = next_venue[b];
    const int nt = next_team[b];
    const int no = next_opp[b];

    // ---- packed stream loads: 2 idx-quads + 4 goal-pairs per thread ----
    const int q0 = b * 64 + lane;        // quad of positions lane*4..lane*4+3
    const int q1 = q0 + 32;              // positions 128+lane*4..
    const uint4  pa  = ((const uint4*)g_pidx)[q0];
    const uint4  pb  = ((const uint4*)g_pidx)[q1];
    const float4 ga0 = ((const float4*)g_pgoals)[2 * q0];
    const float4 ga1 = ((const float4*)g_pgoals)[2 * q0 + 1];
    const float4 gb0 = ((const float4*)g_pgoals)[2 * q1];
    const float4 gb1 = ((const float4*)g_pgoals)[2 * q1 + 1];

    // ---- stage this warp's two Gram rows (coalesced) ----
    const float4* src1 = (const float4*)(g_G + nt * NTP);
    const float4* src2 = (const float4*)(g_G + no * NTP);
    float4* dst1 = (float4*)(rows + w * 2048);
    float4* dst2 = (float4*)(rows + w * 2048 + 1024);
    #pragma unroll
    for (int i = 0; i < 8; i++) {
        dst1[lane + 32 * i] = src1[lane + 32 * i];
        dst2[lane + 32 * i] = src2[lane + 32 * i];
    }
    // ---- stage tables (block-cooperative, coalesced) ----
    #pragma unroll
    for (int i = 0; i < 4; i++) {
        PT1s[tid + 256 * i] = g_PT1[tid + 256 * i];
        PT2s[tid + 256 * i] = g_PT2[tid + 256 * i];
    }
    if (tid < 9) { PVRs[tid] = g_PVR[tid]; Gvens[tid] = g_Gven[tid]; }

    const unsigned int pp[8] = {pa.x, pa.y, pa.z, pa.w, pb.x, pb.y, pb.z, pb.w};
    int vv[8], tt[8], oo[8], rr[8];
    #pragma unroll
    for (int j = 0; j < 8; j++) {
        vv[j] = pp[j] & 3u;
        tt[j] = (pp[j] >> 2) & 1023u;
        oo[j] = (pp[j] >> 12) & 1023u;
        rr[j] = (pp[j] >> 22) & 3u;
    }
    const float gfv[8] = {ga0.x, ga0.z, ga1.x, ga1.z, gb0.x, gb0.z, gb1.x, gb1.z};
    const float gav[8] = {ga0.y, ga0.w, ga1.y, ga1.w, gb0.y, gb0.w, gb1.y, gb1.w};

    __syncthreads();

    const float* rw0 = rows + w * 2048;
    const float* rw1 = rows + w * 2048 + 1024;

    const float inv_scale = 0.051031036307982884f;  // 1/sqrt(384)
    float s[8];
    #pragma unroll
    for (int j = 0; j < 8; j++)
        s[j] = (Gvens[vv[j] * 3 + nv] + rw0[tt[j]] + rw1[oo[j]]) * inv_scale;

    float m = s[0];
    #pragma unroll
    for (int j = 1; j < 8; j++) m = fmaxf(m, s[j]);
    #pragma unroll
    for (int off = 16; off; off >>= 1)
        m = fmaxf(m, __shfl_xor_sync(0xffffffffu, m, off));

    float e[8], su = 0.0f;
    #pragma unroll
    for (int j = 0; j < 8; j++) { e[j] = __expf(s[j] - m); su += e[j]; }
    #pragma unroll
    for (int off = 16; off; off >>= 1)
        su += __shfl_xor_sync(0xffffffffu, su, off);
    const float inv = __frcp_rn(su);

    const float wgf0 = W[512 * 3 + 0], wgf1 = W[512 * 3 + 1], wgf2 = W[512 * 3 + 2];
    const float wga0 = W[513 * 3 + 0], wga1 = W[513 * 3 + 1], wga2 = W[513 * 3 + 2];

    float c0 = 0, c1 = 0, c2 = 0;
    #pragma unroll
    for (int j = 0; j < 8; j++) {
        const float a = e[j] * inv;
        const float4 p1  = PT1s[tt[j]];
        const float4 p2  = PT2s[oo[j]];
        const float4 pvr = PVRs[vv[j] * 3 + rr[j]];
        c0 += a * (p1.x + p2.x + pvr.x + gfv[j] * wgf0 + gav[j] * wga0);
        c1 += a * (p1.y + p2.y + pvr.y + gfv[j] * wgf1 + gav[j] * wga1);
        c2 += a * (p1.z + p2.z + pvr.z + gfv[j] * wgf2 + gav[j] * wga2);
    }
    #pragma unroll
    for (int off = 16; off; off >>= 1) {
        c0 += __shfl_xor_sync(0xffffffffu, c0, off);
        c1 += __shfl_xor_sync(0xffffffffu, c1, off);
        c2 += __shfl_xor_sync(0xffffffffu, c2, off);
    }

    if (lane == 0) {
        const float s0 = stats[b * 3 + 0], s1 = stats[b * 3 + 1], s2 = stats[b * 3 + 2];
        c0 += s0 * W[514 * 3 + 0] + s1 * W[515 * 3 + 0] + s2 * W[516 * 3 + 0] + b_out[0];
        c1 += s0 * W[514 * 3 + 1] + s1 * W[515 * 3 + 1] + s2 * W[516 * 3 + 1] + b_out[1];
        c2 += s0 * W[514 * 3 + 2] + s1 * W[515 * 3 + 2] + s2 * W[516 * 3 + 2] + b_out[2];
        out[b * 3 + 0] = c0;
        out[b * 3 + 1] = c1;
        out[b * 3 + 2] = c2;
    }
}

// ---------------------------------------------------------------------------
extern "C" void kernel_launch(void* const* d_in, const int* in_sizes, int n_in,
                              void* d_out, int out_size) {
    const float* team_embed    = (const float*)d_in[0];
    const float* venue_embed   = (const float*)d_in[1];
    const float* result_embed  = (const float*)d_in[2];
    const float* W_out         = (const float*)d_in[3];
    const float* b_out         = (const float*)d_in[4];
    const float* goals_for     = (const float*)d_in[5];
    const float* goals_against = (const float*)d_in[6];
    const float* stats         = (const float*)d_in[7];
    const int*   venue         = (const int*)d_in[8];
    const int*   team          = (const int*)d_in[9];
    const int*   opponent      = (const int*)d_in[10];
    const int*   result        = (const int*)d_in[11];
    const int*   next_venue    = (const int*)d_in[12];
    const int*   next_team     = (const int*)d_in[13];
    const int*   next_opponent = (const int*)d_in[14];
    float* out = (float*)d_out;

    cudaFuncSetAttribute(main_kernel,
                         cudaFuncAttributeMaxDynamicSharedMemorySize,
                         MAIN_SMEM_BYTES);

    prep_gram_kernel<<<NBLK, 256>>>(team_embed, venue_embed,
                                    result_embed, W_out,
                                    venue, team, opponent, result,
                                    goals_for, goals_against);

    main_kernel<<<128, 256, MAIN_SMEM_BYTES>>>(
        stats, next_venue, next_team, next_opponent,
        W_out, b_out, out);
}